// round 14
// baseline (speedup 1.0000x reference)
#include <cuda_runtime.h>
#include <math_constants.h>
#include <cstdint>

#define BATCH 4096
#define DIM 256
#define NEG_INF (-CUDART_INF_F)

// ---------------- static scratch ----------------
__device__ char g_ai8[BATCH * DIM];          // normalized, row-scaled int8
__device__ char g_p0i8[BATCH * DIM];
__device__ char g_p1i8[BATCH * DIM];
__device__ float g_sa[BATCH];                // per-row dequant scales
__device__ float g_s0[BATCH];
__device__ float g_s1[BATCH];
__device__ float g_posdot[2][BATCH];         // fp32 exact positive dots
__device__ unsigned g_maxbits[2][BATCH];

// ---------------- helpers ----------------
__device__ __forceinline__ unsigned enc_f(float f) {
    unsigned u = __float_as_uint(f);
    return (u & 0x80000000u) ? ~u : (u | 0x80000000u);
}
__device__ __forceinline__ float dec_f(unsigned u) {
    u = (u & 0x80000000u) ? (u & 0x7FFFFFFFu) : ~u;
    return __uint_as_float(u);
}
__device__ __forceinline__ uint32_t smem_u32(const void* p) {
    uint32_t a;
    asm("{ .reg .u64 t; cvta.to.shared.u64 t, %1; cvt.u32.u64 %0, t; }" : "=r"(a) : "l"(p));
    return a;
}
__device__ __forceinline__ void cp_async16(uint32_t dst, const void* src) {
    asm volatile("cp.async.cg.shared.global [%0], [%1], 16;" :: "r"(dst), "l"(src) : "memory");
}
#define CP_COMMIT() asm volatile("cp.async.commit_group;" ::: "memory")
#define CP_WAIT0()  asm volatile("cp.async.wait_group 0;" ::: "memory")

__device__ __forceinline__ void ldsm_x4(uint32_t& r0, uint32_t& r1, uint32_t& r2, uint32_t& r3,
                                        uint32_t addr) {
    asm volatile("ldmatrix.sync.aligned.m8n8.x4.shared.b16 {%0,%1,%2,%3}, [%4];"
                 : "=r"(r0), "=r"(r1), "=r"(r2), "=r"(r3) : "r"(addr));
}
// int8 MMA: D(s32) += A(s8,16x32) * B(s8,32x8)
__device__ __forceinline__ void mma_i8(int* c, const uint32_t* a, const uint32_t* b) {
    asm volatile(
        "mma.sync.aligned.m16n8k32.row.col.s32.s8.s8.s32 "
        "{%0,%1,%2,%3}, {%4,%5,%6,%7}, {%8,%9}, {%0,%1,%2,%3};"
        : "+r"(c[0]), "+r"(c[1]), "+r"(c[2]), "+r"(c[3])
        : "r"(a[0]), "r"(a[1]), "r"(a[2]), "r"(a[3]), "r"(b[0]), "r"(b[1]));
}

// ---------------- kernel 1: normalize + posdot + int8 quantize ----------------
// One block of 64 threads per batch row.
__global__ void norm_kernel(const float* __restrict__ anchor,
                            const float* __restrict__ positive) {
    int i = blockIdx.x;
    int tid = threadIdx.x;                       // 0..63
    float4 a  = ((const float4*)(anchor  + (size_t)i * DIM))[tid];
    float4 p0 = ((const float4*)(positive + (size_t)i * 2 * DIM))[tid];
    float4 p1 = ((const float4*)(positive + (size_t)i * 2 * DIM + DIM))[tid];

    float s[5];
    s[0] = a.x * a.x + a.y * a.y + a.z * a.z + a.w * a.w;
    s[1] = p0.x * p0.x + p0.y * p0.y + p0.z * p0.z + p0.w * p0.w;
    s[2] = p1.x * p1.x + p1.y * p1.y + p1.z * p1.z + p1.w * p1.w;
    s[3] = a.x * p0.x + a.y * p0.y + a.z * p0.z + a.w * p0.w;
    s[4] = a.x * p1.x + a.y * p1.y + a.z * p1.z + a.w * p1.w;
    float ma = fmaxf(fmaxf(fabsf(a.x), fabsf(a.y)), fmaxf(fabsf(a.z), fabsf(a.w)));
    float m0 = fmaxf(fmaxf(fabsf(p0.x), fabsf(p0.y)), fmaxf(fabsf(p0.z), fabsf(p0.w)));
    float m1 = fmaxf(fmaxf(fabsf(p1.x), fabsf(p1.y)), fmaxf(fabsf(p1.z), fabsf(p1.w)));
#pragma unroll
    for (int o = 16; o; o >>= 1) {
#pragma unroll
        for (int k = 0; k < 5; k++) s[k] += __shfl_xor_sync(0xffffffffu, s[k], o);
        ma = fmaxf(ma, __shfl_xor_sync(0xffffffffu, ma, o));
        m0 = fmaxf(m0, __shfl_xor_sync(0xffffffffu, m0, o));
        m1 = fmaxf(m1, __shfl_xor_sync(0xffffffffu, m1, o));
    }
    __shared__ float ws[2][8];
    if ((tid & 31) == 0) {
#pragma unroll
        for (int k = 0; k < 5; k++) ws[tid >> 5][k] = s[k];
        ws[tid >> 5][5] = ma; ws[tid >> 5][6] = m0; ws[tid >> 5][7] = m1;
    }
    __syncthreads();
    float na = ws[0][0] + ws[1][0];
    float n0 = ws[0][1] + ws[1][1];
    float n1 = ws[0][2] + ws[1][2];
    float d0 = ws[0][3] + ws[1][3];
    float d1 = ws[0][4] + ws[1][4];
    float Ma = fmaxf(ws[0][5], ws[1][5]);
    float M0 = fmaxf(ws[0][6], ws[1][6]);
    float M1 = fmaxf(ws[0][7], ws[1][7]);
    float ia = 1.0f / fmaxf(sqrtf(na), 1e-12f);
    float i0 = 1.0f / fmaxf(sqrtf(n0), 1e-12f);
    float i1 = 1.0f / fmaxf(sqrtf(n1), 1e-12f);

    // quant scales on NORMALIZED values: maxnorm = maxraw * inv
    float sca = fmaxf(Ma * ia, 1e-12f) * (1.0f / 127.0f);
    float sc0 = fmaxf(M0 * i0, 1e-12f) * (1.0f / 127.0f);
    float sc1 = fmaxf(M1 * i1, 1e-12f) * (1.0f / 127.0f);

    if (tid == 0) {
        g_posdot[0][i] = d0 * ia * i0;
        g_posdot[1][i] = d1 * ia * i1;
        g_maxbits[0][i] = 0u;
        g_maxbits[1][i] = 0u;
        g_sa[i] = sca; g_s0[i] = sc0; g_s1[i] = sc1;
    }

    auto quant4 = [](float4 v, float mul) {
        int q0 = __float2int_rn(v.x * mul);
        int q1 = __float2int_rn(v.y * mul);
        int q2 = __float2int_rn(v.z * mul);
        int q3 = __float2int_rn(v.w * mul);
        return make_char4((char)q0, (char)q1, (char)q2, (char)q3);
    };
    float qa = ia / sca, q0m = i0 / sc0, q1m = i1 / sc1;
    ((char4*)(g_ai8  + (size_t)i * DIM))[tid] = quant4(a, qa);
    ((char4*)(g_p0i8 + (size_t)i * DIM))[tid] = quant4(p0, q0m);
    ((char4*)(g_p1i8 + (size_t)i * DIM))[tid] = quant4(p1, q1m);
}

// ---------------- kernel 2: int8 mma GEMM + masked max ----------------
// CTA tile 128x128, 8 warps (2m x 4n), warp tile 64x32. Full K=256 int8
// (256B/row) resident in smem: NO pipeline, one sync before compute.
// kb^(row&7) 16B swizzle (8 units per 128B chunk; 2 chunks per row).
// Compact 1-D grid of 2576 blocks (R10 decode): src1/src2 dense, src0 triangle.
#define TILE 128
#define CHUNK 16384                    // 128 rows x 128B
#define SM_LABC 0
#define SM_LABR 512
#define SM_MAXR 1024
#define SM_MAXC 1536
#define SM_SROW 2048                   // float[128]
#define SM_SCOL 2560                   // float[128]
#define SM_BUF  3072
#define SM_TOTAL (SM_BUF + 4 * CHUNK)  // 68608: A c0, A c1, B c0, B c1

__global__ __launch_bounds__(256, 2) void gemm_max_kernel(const int* __restrict__ labels) {
    int bid = blockIdx.x;
    int src, rtile, ctile;
    if (bid < 2048) {
        src = 1 + (bid >> 10);
        int t = bid & 1023;
        rtile = t >> 5;
        ctile = t & 31;
    } else {
        src = 0;
        int t = bid - 2048;                     // 0..527 -> upper triangle
        int r = (int)(32.5f - sqrtf(1056.25f - 2.0f * (float)t));
        while (32 * r - r * (r - 1) / 2 > t) r--;
        while (32 * (r + 1) - (r + 1) * r / 2 <= t) r++;
        rtile = r;
        ctile = r + (t - (32 * r - r * (r - 1) / 2));
    }
    bool colfold = (src == 0) && (ctile > rtile);

    extern __shared__ char smem[];
    uint32_t smem_base = smem_u32(smem);
    int tid = threadIdx.x;
    int wid = tid >> 5, lane = tid & 31;
    int wm = wid >> 2;                 // 0..1
    int wn = wid & 3;                  // 0..3

    int colbase = ctile * TILE;
    int row0 = rtile * TILE;
    const char* Bmat = (src == 0) ? g_ai8 : (src == 1 ? g_p0i8 : g_p1i8);
    const float* Bscale = (src == 0) ? g_sa : (src == 1 ? g_s0 : g_s1);

    if (tid < TILE) {
        *(int*)(smem + SM_LABC + tid * 4) = labels[colbase + tid];
        *(int*)(smem + SM_LABR + tid * 4) = labels[row0 + tid];
        *(unsigned*)(smem + SM_MAXR + tid * 4) = 0u;
        *(unsigned*)(smem + SM_MAXC + tid * 4) = 0u;
        *(float*)(smem + SM_SROW + tid * 4) = g_sa[row0 + tid];
        *(float*)(smem + SM_SCOL + tid * 4) = Bscale[colbase + tid];
    }

    const char* gA = g_ai8 + (size_t)row0 * DIM;
    const char* gB = Bmat + (size_t)colbase * DIM;

    // Load ALL of A and B (2 chunks each) with 16B swizzled stores.
    // Per matrix: 2048 16B-units; 8 cp.async per thread per matrix.
    {
        uint32_t abase = smem_base + SM_BUF;
        uint32_t bbase = abase + 2 * CHUNK;
#pragma unroll
        for (int i = 0; i < 8; i++) {
            int id = tid + i * 256;            // 0..2047
            int ch = id >> 10, rem = id & 1023;
            int row = rem >> 3, kb = rem & 7;
            uint32_t off = ch * CHUNK + row * 128 + ((kb ^ (row & 7)) << 4);
            cp_async16(abase + off, gA + row * 256 + ch * 128 + kb * 16);
        }
#pragma unroll
        for (int i = 0; i < 8; i++) {
            int id = tid + i * 256;
            int ch = id >> 10, rem = id & 1023;
            int row = rem >> 3, kb = rem & 7;
            uint32_t off = ch * CHUNK + row * 128 + ((kb ^ (row & 7)) << 4);
            cp_async16(bbase + off, gB + row * 256 + ch * 128 + kb * 16);
        }
    }
    CP_COMMIT();

    int acc[4][4][4];
#pragma unroll
    for (int i = 0; i < 4; i++)
#pragma unroll
        for (int j = 0; j < 4; j++)
#pragma unroll
            for (int k = 0; k < 4; k++) acc[i][j][k] = 0;

    int arow_lo = wm * 64 + (lane & 15);
    int brow_lo = wn * 32 + (lane & 7) + ((lane >> 4) << 3);
    int a_kb_lo = lane >> 4;           // 16B-unit within k32 slice
    int b_kb_lo = (lane >> 3) & 1;

    CP_WAIT0();
    __syncthreads();

#pragma unroll
    for (int kc = 0; kc < 2; kc++) {
        uint32_t abase = smem_base + SM_BUF + kc * CHUNK;
        uint32_t bbase = smem_base + SM_BUF + 2 * CHUNK + kc * CHUNK;
#pragma unroll
        for (int ks = 0; ks < 4; ks++) {       // k32 slices within 128B chunk
            uint32_t a[4][4];
            int akb = 2 * ks + a_kb_lo;
#pragma unroll
            for (int mf = 0; mf < 4; mf++) {
                int row = arow_lo + mf * 16;
                uint32_t addr = abase + row * 128 + ((akb ^ (row & 7)) << 4);
                ldsm_x4(a[mf][0], a[mf][1], a[mf][2], a[mf][3], addr);
            }
            uint32_t b[4][2];
            int bkb = 2 * ks + b_kb_lo;
#pragma unroll
            for (int nf2 = 0; nf2 < 2; nf2++) {
                int row = brow_lo + nf2 * 16;
                uint32_t addr = bbase + row * 128 + ((bkb ^ (row & 7)) << 4);
                uint32_t r0, r1, r2, r3;
                ldsm_x4(r0, r1, r2, r3, addr);
                b[nf2 * 2][0] = r0; b[nf2 * 2][1] = r1;
                b[nf2 * 2 + 1][0] = r2; b[nf2 * 2 + 1][1] = r3;
            }
#pragma unroll
            for (int mf = 0; mf < 4; mf++)
#pragma unroll
                for (int nfi = 0; nfi < 4; nfi++)
                    mma_i8(acc[mf][nfi], a[mf], b[nfi]);
        }
    }
    __syncthreads();

    // ---- epilogue: dequantize + label-masked max ----
    int g = lane >> 2, tg = lane & 3;
    const int* labC = (const int*)(smem + SM_LABC);
    const int* labR = (const int*)(smem + SM_LABR);
    const float* sRow = (const float*)(smem + SM_SROW);
    const float* sCol = (const float*)(smem + SM_SCOL);
    unsigned* smaxr = (unsigned*)(smem + SM_MAXR);
    unsigned* smaxc = (unsigned*)(smem + SM_MAXC);

    // row-fold
#pragma unroll
    for (int mf = 0; mf < 4; mf++) {
#pragma unroll
        for (int h = 0; h < 2; h++) {
            int row = wm * 64 + mf * 16 + g + h * 8;
            int rl = labR[row];
            float sr = sRow[row];
            float m = NEG_INF;
#pragma unroll
            for (int nfi = 0; nfi < 4; nfi++) {
                int col = wn * 32 + nfi * 8 + 2 * tg;
                float f0 = (float)acc[mf][nfi][h * 2 + 0] * (sr * sCol[col]);
                float f1 = (float)acc[mf][nfi][h * 2 + 1] * (sr * sCol[col + 1]);
                if (labC[col] != rl)     m = fmaxf(m, f0);
                if (labC[col + 1] != rl) m = fmaxf(m, f1);
            }
            atomicMax(&smaxr[row], enc_f(m));
        }
    }

    // col-fold (mirror of symmetric src0 tiles)
    if (colfold) {
#pragma unroll
        for (int nfi = 0; nfi < 4; nfi++) {
#pragma unroll
            for (int cpos = 0; cpos < 2; cpos++) {
                int col = wn * 32 + nfi * 8 + 2 * tg + cpos;
                int cl = labC[col];
                float sc = sCol[col];
                float m = NEG_INF;
#pragma unroll
                for (int mf = 0; mf < 4; mf++) {
#pragma unroll
                    for (int h = 0; h < 2; h++) {
                        int row = wm * 64 + mf * 16 + g + h * 8;
                        float f = (float)acc[mf][nfi][h * 2 + cpos] * (sRow[row] * sc);
                        if (labR[row] != cl) m = fmaxf(m, f);
                    }
                }
#pragma unroll
                for (int o = 4; o < 32; o <<= 1) m = fmaxf(m, __shfl_xor_sync(0xffffffffu, m, o));
                if (g == 0) atomicMax(&smaxc[col], enc_f(m));
            }
        }
    }

    __syncthreads();
    if (tid < TILE) {
        unsigned e = smaxr[tid];
        int grow = row0 + tid;
        if (src == 0) {
            atomicMax(&g_maxbits[0][grow], e);
            atomicMax(&g_maxbits[1][grow], e);
            if (colfold) {
                unsigned ec = smaxc[tid];
                int gcol = colbase + tid;
                atomicMax(&g_maxbits[0][gcol], ec);
                atomicMax(&g_maxbits[1][gcol], ec);
            }
        } else {
            atomicMax(&g_maxbits[src - 1][grow], e);
        }
    }
}

// ---------------- kernel 3: fused loss + reduction (single block) ----------------
__global__ void loss_kernel(float* __restrict__ out) {
    int tid = threadIdx.x;                 // 0..1023
    float s = 0.f;
#pragma unroll
    for (int k = 0; k < 8; k++) {
        int idx = tid + k * 1024;
        int v = idx >> 12;
        int i = idx & (BATCH - 1);
        float pd = g_posdot[v][i];
        float nd = dec_f(g_maxbits[v][i]);
        float pos = sqrtf(fmaxf(2.0f - 2.0f * pd, 1e-12f));
        float neg = sqrtf(fmaxf(2.0f - 2.0f * nd, 1e-12f));
        s += fmaxf(pos - neg + 1.0f, 0.0f);
    }
#pragma unroll
    for (int o = 16; o; o >>= 1) s += __shfl_down_sync(0xffffffffu, s, o);
    __shared__ float ws[32];
    if ((tid & 31) == 0) ws[tid >> 5] = s;
    __syncthreads();
    if (tid < 32) {
        float t = ws[tid];
#pragma unroll
        for (int o = 16; o; o >>= 1) t += __shfl_down_sync(0xffffffffu, t, o);
        if (tid == 0) out[0] = t * (1.0f / 8192.0f);
    }
}

// ---------------------------------------------------------------------------
extern "C" void kernel_launch(void* const* d_in, const int* in_sizes, int n_in,
                              void* d_out, int out_size) {
    const float* anchor = (const float*)d_in[0];
    const float* positive = (const float*)d_in[1];
    const int* labels = (const int*)d_in[2];

    cudaFuncSetAttribute(gemm_max_kernel, cudaFuncAttributeMaxDynamicSharedMemorySize, SM_TOTAL);

    norm_kernel<<<BATCH, 64>>>(anchor, positive);
    gemm_max_kernel<<<2576, 256, SM_TOTAL>>>(labels);
    loss_kernel<<<1, 1024>>>((float*)d_out);
}

// round 15
// speedup vs baseline: 1.9947x; 1.9947x over previous
#include <cuda_runtime.h>
#include <cuda_bf16.h>
#include <math_constants.h>
#include <cstdint>

#define BATCH 4096
#define DIM 256
#define NEG_INF (-CUDART_INF_F)

// ---------------- static scratch ----------------
__device__ __nv_bfloat16 g_ab[BATCH * DIM];    // normalized bf16
__device__ __nv_bfloat16 g_p0b[BATCH * DIM];
__device__ __nv_bfloat16 g_p1b[BATCH * DIM];
__device__ float g_posdot[2][BATCH];
__device__ unsigned g_maxbits[2][BATCH];

// ---------------- helpers ----------------
__device__ __forceinline__ unsigned enc_f(float f) {
    unsigned u = __float_as_uint(f);
    return (u & 0x80000000u) ? ~u : (u | 0x80000000u);
}
__device__ __forceinline__ float dec_f(unsigned u) {
    u = (u & 0x80000000u) ? (u & 0x7FFFFFFFu) : ~u;
    return __uint_as_float(u);
}
__device__ __forceinline__ uint32_t smem_u32(const void* p) {
    uint32_t a;
    asm("{ .reg .u64 t; cvta.to.shared.u64 t, %1; cvt.u32.u64 %0, t; }" : "=r"(a) : "l"(p));
    return a;
}
__device__ __forceinline__ void cp_async16(uint32_t dst, const void* src) {
    asm volatile("cp.async.cg.shared.global [%0], [%1], 16;" :: "r"(dst), "l"(src) : "memory");
}
#define CP_COMMIT() asm volatile("cp.async.commit_group;" ::: "memory")
#define CP_WAIT1()  asm volatile("cp.async.wait_group 1;" ::: "memory")

__device__ __forceinline__ void ldsm_x4(uint32_t& r0, uint32_t& r1, uint32_t& r2, uint32_t& r3,
                                        uint32_t addr) {
    asm volatile("ldmatrix.sync.aligned.m8n8.x4.shared.b16 {%0,%1,%2,%3}, [%4];"
                 : "=r"(r0), "=r"(r1), "=r"(r2), "=r"(r3) : "r"(addr));
}
__device__ __forceinline__ void mma16816(float* c, const uint32_t* a, const uint32_t* b) {
    asm volatile(
        "mma.sync.aligned.m16n8k16.row.col.f32.bf16.bf16.f32 "
        "{%0,%1,%2,%3}, {%4,%5,%6,%7}, {%8,%9}, {%0,%1,%2,%3};"
        : "+f"(c[0]), "+f"(c[1]), "+f"(c[2]), "+f"(c[3])
        : "r"(a[0]), "r"(a[1]), "r"(a[2]), "r"(a[3]), "r"(b[0]), "r"(b[1]));
}

// ---------------- kernel 1: fused normalize + positive dots (R10, proven) ----
__global__ void norm_kernel(const float* __restrict__ anchor,
                            const float* __restrict__ positive) {
    int i = blockIdx.x;
    int tid = threadIdx.x;                       // 0..63
    float4 a  = ((const float4*)(anchor  + (size_t)i * DIM))[tid];
    float4 p0 = ((const float4*)(positive + (size_t)i * 2 * DIM))[tid];
    float4 p1 = ((const float4*)(positive + (size_t)i * 2 * DIM + DIM))[tid];

    float s[5];
    s[0] = a.x * a.x + a.y * a.y + a.z * a.z + a.w * a.w;
    s[1] = p0.x * p0.x + p0.y * p0.y + p0.z * p0.z + p0.w * p0.w;
    s[2] = p1.x * p1.x + p1.y * p1.y + p1.z * p1.z + p1.w * p1.w;
    s[3] = a.x * p0.x + a.y * p0.y + a.z * p0.z + a.w * p0.w;
    s[4] = a.x * p1.x + a.y * p1.y + a.z * p1.z + a.w * p1.w;
#pragma unroll
    for (int k = 0; k < 5; k++)
#pragma unroll
        for (int o = 16; o; o >>= 1) s[k] += __shfl_down_sync(0xffffffffu, s[k], o);
    __shared__ float ws[2][5];
    if ((tid & 31) == 0)
#pragma unroll
        for (int k = 0; k < 5; k++) ws[tid >> 5][k] = s[k];
    __syncthreads();
    float na = ws[0][0] + ws[1][0];
    float n0 = ws[0][1] + ws[1][1];
    float n1 = ws[0][2] + ws[1][2];
    float d0 = ws[0][3] + ws[1][3];
    float d1 = ws[0][4] + ws[1][4];
    float ia = 1.0f / fmaxf(sqrtf(na), 1e-12f);
    float i0 = 1.0f / fmaxf(sqrtf(n0), 1e-12f);
    float i1 = 1.0f / fmaxf(sqrtf(n1), 1e-12f);

    if (tid == 0) {
        g_posdot[0][i] = d0 * ia * i0;
        g_posdot[1][i] = d1 * ia * i1;
        g_maxbits[0][i] = 0u;
        g_maxbits[1][i] = 0u;
    }

    uint2 pk;
    __nv_bfloat162 lo, hi;
    lo = __floats2bfloat162_rn(a.x * ia, a.y * ia);
    hi = __floats2bfloat162_rn(a.z * ia, a.w * ia);
    pk.x = *(uint32_t*)&lo; pk.y = *(uint32_t*)&hi;
    ((uint2*)(g_ab + (size_t)i * DIM))[tid] = pk;
    lo = __floats2bfloat162_rn(p0.x * i0, p0.y * i0);
    hi = __floats2bfloat162_rn(p0.z * i0, p0.w * i0);
    pk.x = *(uint32_t*)&lo; pk.y = *(uint32_t*)&hi;
    ((uint2*)(g_p0b + (size_t)i * DIM))[tid] = pk;
    lo = __floats2bfloat162_rn(p1.x * i1, p1.y * i1);
    hi = __floats2bfloat162_rn(p1.z * i1, p1.w * i1);
    pk.x = *(uint32_t*)&lo; pk.y = *(uint32_t*)&hi;
    ((uint2*)(g_p1b + (size_t)i * DIM))[tid] = pk;
}

// ---------------- kernel 2: persistent-A bf16 GEMM + masked max ----------------
// Each CTA: loads A tile (128 rows, FULL K=256, 64KB) once; loops over up to 4
// consecutive 128-col B tiles streamed through a 2x16KB double buffer using the
// R10-proven inner loop. Row-max accumulates in smem across ctiles (1 global
// flush at end). Col-fold per ctile for symmetric src0 tiles.
// Grid 656: [0,256) src1 (rtile 0..31 x cgroup 0..7), [256,512) src2,
//           [512,656) src0 triangle rows grouped in <=4-ctile runs from ctile=rtile.
#define TILE 128
#define B_CHUNK 16384                  // 128 rows x 128B (K=64 slice)
#define A_BYTES 65536                  // 128 rows x 512B (full K)
#define SM_LABC 0
#define SM_LABR 512
#define SM_MAXR 1024
#define SM_MAXC 1536
#define SM_A    2048
#define SM_B    (SM_A + A_BYTES)       // 67584
#define SM_TOTAL (SM_B + 2 * B_CHUNK)  // 100352

__global__ __launch_bounds__(256, 2) void gemm_max_kernel(const int* __restrict__ labels) {
    int bid = blockIdx.x;
    int src, rtile, ctbase, nct;
    if (bid < 512) {
        src = 1 + (bid >> 8);
        int t = bid & 255;
        rtile = t >> 3;
        ctbase = (t & 7) * 4;
        nct = 4;
    } else {
        src = 0;
        int t = bid - 512;                 // 0..143
        int r = 0;
        for (;;) {
            int gr = (35 - r) >> 2;        // ceil((32-r)/4)
            if (t < gr) break;
            t -= gr;
            r++;
        }
        rtile = r;
        ctbase = r + 4 * t;
        int rem = 32 - ctbase;
        nct = rem < 4 ? rem : 4;
    }

    extern __shared__ char smem[];
    uint32_t smem_base = smem_u32(smem);
    int tid = threadIdx.x;
    int wid = tid >> 5, lane = tid & 31;
    int wm = wid >> 2;                 // 0..1
    int wn = wid & 3;                  // 0..3

    int row0 = rtile * TILE;
    const __nv_bfloat16* Bmat = (src == 0) ? g_ab : (src == 1 ? g_p0b : g_p1b);

    if (tid < TILE) {
        *(int*)(smem + SM_LABR + tid * 4) = labels[row0 + tid];
        *(unsigned*)(smem + SM_MAXR + tid * 4) = 0u;
    }

    const char* gA = (const char*)(g_ab + (size_t)row0 * DIM);
    const char* gBbase = (const char*)(Bmat + (size_t)ctbase * TILE * DIM);
    int total_chunks = nct * 4;

    // B chunk c (linear over ctiles): ctile offset c>>2, K-chunk c&3, stage c&1
    auto load_B = [&](int c) {
        const char* gB = gBbase + (size_t)(c >> 2) * TILE * 512;
        int kc = c & 3;
        uint32_t bbase = smem_base + SM_B + (c & 1) * B_CHUNK;
#pragma unroll
        for (int i = 0; i < 4; i++) {
            int id = tid + i * 256;
            int row = id >> 3, kb = id & 7;
            uint32_t off = row * 128 + ((kb ^ (row & 7)) << 4);
            cp_async16(bbase + off, gB + row * 512 + kc * 128 + kb * 16);
        }
    };

    // Load ALL of A (full K, 4096 16B units, 16/thread) + B chunk 0 as group 0.
    {
        uint32_t abase = smem_base + SM_A;
#pragma unroll
        for (int i = 0; i < 16; i++) {
            int id = tid + i * 256;            // 0..4095
            int row = id >> 5, u = id & 31;    // 32 units per row
            int kc = u >> 3, kb = u & 7;
            uint32_t off = row * 512 + kc * 128 + ((kb ^ (row & 7)) << 4);
            cp_async16(abase + off, gA + row * 512 + u * 16);
        }
        load_B(0);
        CP_COMMIT();
        load_B(1);
        CP_COMMIT();
    }

    int arow_lo = wm * 64 + (lane & 15);
    int brow_lo = wn * 32 + (lane & 7) + ((lane >> 4) << 3);
    int a_kb_lo = lane >> 4;
    int b_kb_lo = (lane >> 3) & 1;

    const int* labC = (const int*)(smem + SM_LABC);
    const int* labR = (const int*)(smem + SM_LABR);
    unsigned* smaxr = (unsigned*)(smem + SM_MAXR);
    unsigned* smaxc = (unsigned*)(smem + SM_MAXC);
    int g = lane >> 2, tg = lane & 3;

    for (int ct = 0; ct < nct; ct++) {
        int ctile = ctbase + ct;
        int colbase = ctile * TILE;
        bool colfold = (src == 0) && (ctile > rtile);

        float acc[4][4][4];
#pragma unroll
        for (int i = 0; i < 4; i++)
#pragma unroll
            for (int j = 0; j < 4; j++)
#pragma unroll
                for (int k = 0; k < 4; k++) acc[i][j][k] = 0.f;

#pragma unroll
        for (int kc = 0; kc < 4; kc++) {
            int c = ct * 4 + kc;
            if (c + 1 < total_chunks) load_B(c + 1);
            CP_COMMIT();
            CP_WAIT1();
            __syncthreads();

            uint32_t abase = smem_base + SM_A;   // row*512 + kc*128 addressing
            uint32_t bbase = smem_base + SM_B + (c & 1) * B_CHUNK;
#pragma unroll
            for (int ks = 0; ks < 4; ks++) {
                uint32_t a[4][4];
                int akb = 2 * ks + a_kb_lo;
#pragma unroll
                for (int mf = 0; mf < 4; mf++) {
                    int row = arow_lo + mf * 16;
                    uint32_t addr = abase + row * 512 + kc * 128 + ((akb ^ (row & 7)) << 4);
                    ldsm_x4(a[mf][0], a[mf][1], a[mf][2], a[mf][3], addr);
                }
                uint32_t b[4][2];
                int bkb = 2 * ks + b_kb_lo;
#pragma unroll
                for (int nf2 = 0; nf2 < 2; nf2++) {
                    int row = brow_lo + nf2 * 16;
                    uint32_t addr = bbase + row * 128 + ((bkb ^ (row & 7)) << 4);
                    uint32_t r0, r1, r2, r3;
                    ldsm_x4(r0, r1, r2, r3, addr);
                    b[nf2 * 2][0] = r0; b[nf2 * 2][1] = r1;
                    b[nf2 * 2 + 1][0] = r2; b[nf2 * 2 + 1][1] = r3;
                }
#pragma unroll
                for (int mf = 0; mf < 4; mf++)
#pragma unroll
                    for (int nfi = 0; nfi < 4; nfi++)
                        mma16816(acc[mf][nfi], a[mf], b[nfi]);
            }
            __syncthreads();
        }

        // ---- per-ctile epilogue ----
        if (tid < TILE) {
            *(int*)(smem + SM_LABC + tid * 4) = labels[colbase + tid];
            *(unsigned*)(smem + SM_MAXC + tid * 4) = 0u;
        }
        __syncthreads();

        // row-fold into persistent smaxr
#pragma unroll
        for (int mf = 0; mf < 4; mf++) {
#pragma unroll
            for (int h = 0; h < 2; h++) {
                int row = wm * 64 + mf * 16 + g + h * 8;
                int rl = labR[row];
                float m = NEG_INF;
#pragma unroll
                for (int nfi = 0; nfi < 4; nfi++) {
                    int col = wn * 32 + nfi * 8 + 2 * tg;
                    if (labC[col] != rl)     m = fmaxf(m, acc[mf][nfi][h * 2 + 0]);
                    if (labC[col + 1] != rl) m = fmaxf(m, acc[mf][nfi][h * 2 + 1]);
                }
                atomicMax(&smaxr[row], enc_f(m));
            }
        }

        if (colfold) {
#pragma unroll
            for (int nfi = 0; nfi < 4; nfi++) {
#pragma unroll
                for (int cpos = 0; cpos < 2; cpos++) {
                    int col = wn * 32 + nfi * 8 + 2 * tg + cpos;
                    int cl = labC[col];
                    float m = NEG_INF;
#pragma unroll
                    for (int mf = 0; mf < 4; mf++) {
#pragma unroll
                        for (int h = 0; h < 2; h++) {
                            int row = wm * 64 + mf * 16 + g + h * 8;
                            if (labR[row] != cl) m = fmaxf(m, acc[mf][nfi][h * 2 + cpos]);
                        }
                    }
#pragma unroll
                    for (int o = 4; o < 32; o <<= 1) m = fmaxf(m, __shfl_xor_sync(0xffffffffu, m, o));
                    if (g == 0) atomicMax(&smaxc[col], enc_f(m));
                }
            }
            __syncthreads();
            if (tid < TILE) {
                unsigned ec = smaxc[tid];
                int gcol = colbase + tid;
                atomicMax(&g_maxbits[0][gcol], ec);
                atomicMax(&g_maxbits[1][gcol], ec);
            }
        }
        __syncthreads();
    }

    // ---- final row flush (once per CTA) ----
    if (tid < TILE) {
        unsigned e = smaxr[tid];
        int grow = row0 + tid;
        if (src == 0) {
            atomicMax(&g_maxbits[0][grow], e);
            atomicMax(&g_maxbits[1][grow], e);
        } else {
            atomicMax(&g_maxbits[src - 1][grow], e);
        }
    }
}

// ---------------- kernel 3: fused loss + reduction (single block) ----------------
__global__ void loss_kernel(float* __restrict__ out) {
    int tid = threadIdx.x;                 // 0..1023
    float s = 0.f;
#pragma unroll
    for (int k = 0; k < 8; k++) {
        int idx = tid + k * 1024;
        int v = idx >> 12;
        int i = idx & (BATCH - 1);
        float pd = g_posdot[v][i];
        float nd = dec_f(g_maxbits[v][i]);
        float pos = sqrtf(fmaxf(2.0f - 2.0f * pd, 1e-12f));
        float neg = sqrtf(fmaxf(2.0f - 2.0f * nd, 1e-12f));
        s += fmaxf(pos - neg + 1.0f, 0.0f);
    }
#pragma unroll
    for (int o = 16; o; o >>= 1) s += __shfl_down_sync(0xffffffffu, s, o);
    __shared__ float ws[32];
    if ((tid & 31) == 0) ws[tid >> 5] = s;
    __syncthreads();
    if (tid < 32) {
        float t = ws[tid];
#pragma unroll
        for (int o = 16; o; o >>= 1) t += __shfl_down_sync(0xffffffffu, t, o);
        if (tid == 0) out[0] = t * (1.0f / 8192.0f);
    }
}

// ---------------------------------------------------------------------------
extern "C" void kernel_launch(void* const* d_in, const int* in_sizes, int n_in,
                              void* d_out, int out_size) {
    const float* anchor = (const float*)d_in[0];
    const float* positive = (const float*)d_in[1];
    const int* labels = (const int*)d_in[2];

    cudaFuncSetAttribute(gemm_max_kernel, cudaFuncAttributeMaxDynamicSharedMemorySize, SM_TOTAL);

    norm_kernel<<<BATCH, 64>>>(anchor, positive);
    gemm_max_kernel<<<656, 256, SM_TOTAL>>>(labels);
    loss_kernel<<<1, 1024>>>((float*)d_out);
}

// round 16
// speedup vs baseline: 2.1474x; 1.0766x over previous
#include <cuda_runtime.h>
#include <cuda_fp16.h>
#include <math_constants.h>
#include <cstdint>

#define BATCH 4096
#define DIM 256
#define NEG_INF (-CUDART_INF_F)

// ---------------- static scratch ----------------
__device__ __half g_ah[BATCH * DIM];           // normalized f16
__device__ __half g_p0h[BATCH * DIM];
__device__ __half g_p1h[BATCH * DIM];
__device__ float g_posdot[2][BATCH];
__device__ unsigned g_maxbits[2][BATCH];

// ---------------- helpers ----------------
__device__ __forceinline__ unsigned enc_f(float f) {
    unsigned u = __float_as_uint(f);
    return (u & 0x80000000u) ? ~u : (u | 0x80000000u);
}
__device__ __forceinline__ float dec_f(unsigned u) {
    u = (u & 0x80000000u) ? (u & 0x7FFFFFFFu) : ~u;
    return __uint_as_float(u);
}
__device__ __forceinline__ uint32_t smem_u32(const void* p) {
    uint32_t a;
    asm("{ .reg .u64 t; cvta.to.shared.u64 t, %1; cvt.u32.u64 %0, t; }" : "=r"(a) : "l"(p));
    return a;
}
__device__ __forceinline__ void cp_async16(uint32_t dst, const void* src) {
    asm volatile("cp.async.cg.shared.global [%0], [%1], 16;" :: "r"(dst), "l"(src) : "memory");
}
#define CP_COMMIT() asm volatile("cp.async.commit_group;" ::: "memory")
#define CP_WAIT1()  asm volatile("cp.async.wait_group 1;" ::: "memory")

__device__ __forceinline__ void ldsm_x4(uint32_t& r0, uint32_t& r1, uint32_t& r2, uint32_t& r3,
                                        uint32_t addr) {
    asm volatile("ldmatrix.sync.aligned.m8n8.x4.shared.b16 {%0,%1,%2,%3}, [%4];"
                 : "=r"(r0), "=r"(r1), "=r"(r2), "=r"(r3) : "r"(addr));
}
// f16 inputs, f16 accumulator: C fragment = 2 x .f16x2 regs
__device__ __forceinline__ void mma_f16acc(uint32_t* c, const uint32_t* a, const uint32_t* b) {
    asm volatile(
        "mma.sync.aligned.m16n8k16.row.col.f16.f16.f16.f16 "
        "{%0,%1}, {%2,%3,%4,%5}, {%6,%7}, {%0,%1};"
        : "+r"(c[0]), "+r"(c[1])
        : "r"(a[0]), "r"(a[1]), "r"(a[2]), "r"(a[3]), "r"(b[0]), "r"(b[1]));
}

// ---------------- kernel 1: fused normalize + positive dots ----------------
__global__ void norm_kernel(const float* __restrict__ anchor,
                            const float* __restrict__ positive) {
    int i = blockIdx.x;
    int tid = threadIdx.x;                       // 0..63
    float4 a  = ((const float4*)(anchor  + (size_t)i * DIM))[tid];
    float4 p0 = ((const float4*)(positive + (size_t)i * 2 * DIM))[tid];
    float4 p1 = ((const float4*)(positive + (size_t)i * 2 * DIM + DIM))[tid];

    float s[5];
    s[0] = a.x * a.x + a.y * a.y + a.z * a.z + a.w * a.w;
    s[1] = p0.x * p0.x + p0.y * p0.y + p0.z * p0.z + p0.w * p0.w;
    s[2] = p1.x * p1.x + p1.y * p1.y + p1.z * p1.z + p1.w * p1.w;
    s[3] = a.x * p0.x + a.y * p0.y + a.z * p0.z + a.w * p0.w;
    s[4] = a.x * p1.x + a.y * p1.y + a.z * p1.z + a.w * p1.w;
#pragma unroll
    for (int k = 0; k < 5; k++)
#pragma unroll
        for (int o = 16; o; o >>= 1) s[k] += __shfl_down_sync(0xffffffffu, s[k], o);
    __shared__ float ws[2][5];
    if ((tid & 31) == 0)
#pragma unroll
        for (int k = 0; k < 5; k++) ws[tid >> 5][k] = s[k];
    __syncthreads();
    float na = ws[0][0] + ws[1][0];
    float n0 = ws[0][1] + ws[1][1];
    float n1 = ws[0][2] + ws[1][2];
    float d0 = ws[0][3] + ws[1][3];
    float d1 = ws[0][4] + ws[1][4];
    float ia = 1.0f / fmaxf(sqrtf(na), 1e-12f);
    float i0 = 1.0f / fmaxf(sqrtf(n0), 1e-12f);
    float i1 = 1.0f / fmaxf(sqrtf(n1), 1e-12f);

    if (tid == 0) {
        g_posdot[0][i] = d0 * ia * i0;
        g_posdot[1][i] = d1 * ia * i1;
        g_maxbits[0][i] = 0u;
        g_maxbits[1][i] = 0u;
    }

    uint2 pk;
    __half2 lo, hi;
    lo = __floats2half2_rn(a.x * ia, a.y * ia);
    hi = __floats2half2_rn(a.z * ia, a.w * ia);
    pk.x = *(uint32_t*)&lo; pk.y = *(uint32_t*)&hi;
    ((uint2*)(g_ah + (size_t)i * DIM))[tid] = pk;
    lo = __floats2half2_rn(p0.x * i0, p0.y * i0);
    hi = __floats2half2_rn(p0.z * i0, p0.w * i0);
    pk.x = *(uint32_t*)&lo; pk.y = *(uint32_t*)&hi;
    ((uint2*)(g_p0h + (size_t)i * DIM))[tid] = pk;
    lo = __floats2half2_rn(p1.x * i1, p1.y * i1);
    hi = __floats2half2_rn(p1.z * i1, p1.w * i1);
    pk.x = *(uint32_t*)&lo; pk.y = *(uint32_t*)&hi;
    ((uint2*)(g_p1h + (size_t)i * DIM))[tid] = pk;
}

// ---------------- kernel 2: f16-acc mma GEMM + masked max ----------------
// CTA tile 128x256, 8 warps (2m x 4n), warp tile 64x64, K chunks of 64,
// 2-stage cp.async pipeline, kb^(row&7) swizzle, f16 accumulators (64 regs),
// target occupancy 2. Grid 1296 (R13 decode): src1/src2 dense 512 each,
// src0 triangle 272 tile-pairs, col-fold for mirror coverage.
#define TILE_M 128
#define TILE_N 256
#define A_CHUNK (128 * 128)
#define B_CHUNK (256 * 128)
#define STAGE_BYTES (A_CHUNK + B_CHUNK)
#define SM_LABC 0                      // 1024 B
#define SM_LABR 1024                   // 512 B
#define SM_MAXR 1536                   // 512 B
#define SM_MAXC 2048                   // 1024 B
#define SM_BUF  3072
#define SM_TOTAL (SM_BUF + 2 * STAGE_BYTES)   // 101376

__global__ __launch_bounds__(256, 2) void gemm_max_kernel(const int* __restrict__ labels) {
    int bid = blockIdx.x;
    int src, rtile, cpair;
    if (bid < 1024) {
        src = 1 + (bid >> 9);
        int t = bid & 511;
        rtile = t >> 4;
        cpair = t & 15;
    } else {
        src = 0;
        int t = bid - 1024;                 // 0..271
        int k = 0, base = 0;
        while (base + 2 * (16 - k) <= t) { base += 2 * (16 - k); k++; }
        int off = t - base;
        int n = 16 - k;
        rtile = 2 * k + (off >= n);
        cpair = k + (off >= n ? off - n : off);
    }

    extern __shared__ char smem[];
    uint32_t smem_base = smem_u32(smem);
    int tid = threadIdx.x;
    int wid = tid >> 5, lane = tid & 31;
    int wm = wid >> 2;                 // 0..1
    int wn = wid & 3;                  // 0..3

    int colbase = cpair * TILE_N;
    int row0 = rtile * TILE_M;
    const __half* Bmat = (src == 0) ? g_ah : (src == 1 ? g_p0h : g_p1h);

    bool cf_any = (src == 0) && (2 * cpair + 1 > rtile);

    if (tid < TILE_N) *(int*)(smem + SM_LABC + tid * 4) = labels[colbase + tid];
    if (tid < TILE_M) {
        *(int*)(smem + SM_LABR + tid * 4) = labels[row0 + tid];
        *(unsigned*)(smem + SM_MAXR + tid * 4) = 0u;
    }
    if (tid < TILE_N) *(unsigned*)(smem + SM_MAXC + tid * 4) = 0u;

    const char* gA = (const char*)(g_ah + (size_t)row0 * DIM);
    const char* gB = (const char*)(Bmat + (size_t)colbase * DIM);

    auto load_stage = [&](int s, int kc) {
        uint32_t abase = smem_base + SM_BUF + s * STAGE_BYTES;
        uint32_t bbase = abase + A_CHUNK;
#pragma unroll
        for (int i = 0; i < 4; i++) {
            int id = tid + i * 256;
            int row = id >> 3, kb = id & 7;
            uint32_t off = row * 128 + ((kb ^ (row & 7)) << 4);
            cp_async16(abase + off, gA + row * 512 + kc * 128 + kb * 16);
        }
#pragma unroll
        for (int i = 0; i < 8; i++) {
            int id = tid + i * 256;
            int row = id >> 3, kb = id & 7;
            uint32_t off = row * 128 + ((kb ^ (row & 7)) << 4);
            cp_async16(bbase + off, gB + row * 512 + kc * 128 + kb * 16);
        }
    };

    uint32_t acc[4][8][2];             // f16x2 accumulators
#pragma unroll
    for (int i = 0; i < 4; i++)
#pragma unroll
        for (int j = 0; j < 8; j++) { acc[i][j][0] = 0u; acc[i][j][1] = 0u; }

    int arow_lo = wm * 64 + (lane & 15);
    int brow_lo = wn * 64 + (lane & 7) + ((lane >> 4) << 3);
    int a_kb_lo = lane >> 4;
    int b_kb_lo = (lane >> 3) & 1;

    load_stage(0, 0);
    CP_COMMIT();

#pragma unroll
    for (int kc = 0; kc < 4; kc++) {
        if (kc < 3) load_stage((kc + 1) & 1, kc + 1);
        CP_COMMIT();
        CP_WAIT1();
        __syncthreads();

        uint32_t abase = smem_base + SM_BUF + (kc & 1) * STAGE_BYTES;
        uint32_t bbase = abase + A_CHUNK;
#pragma unroll
        for (int ks = 0; ks < 4; ks++) {
            uint32_t a[4][4];
            int akb = 2 * ks + a_kb_lo;
#pragma unroll
            for (int mf = 0; mf < 4; mf++) {
                int row = arow_lo + mf * 16;
                uint32_t addr = abase + row * 128 + ((akb ^ (row & 7)) << 4);
                ldsm_x4(a[mf][0], a[mf][1], a[mf][2], a[mf][3], addr);
            }
            uint32_t b[8][2];
            int bkb = 2 * ks + b_kb_lo;
#pragma unroll
            for (int nf2 = 0; nf2 < 4; nf2++) {
                int row = brow_lo + nf2 * 16;
                uint32_t addr = bbase + row * 128 + ((bkb ^ (row & 7)) << 4);
                uint32_t r0, r1, r2, r3;
                ldsm_x4(r0, r1, r2, r3, addr);
                b[nf2 * 2][0] = r0; b[nf2 * 2][1] = r1;
                b[nf2 * 2 + 1][0] = r2; b[nf2 * 2 + 1][1] = r3;
            }
#pragma unroll
            for (int mf = 0; mf < 4; mf++)
#pragma unroll
                for (int nfi = 0; nfi < 8; nfi++)
                    mma_f16acc(acc[mf][nfi], a[mf], b[nfi]);
        }
        __syncthreads();
    }

    // ---- epilogue ----
    int g = lane >> 2, tg = lane & 3;
    const int* labC = (const int*)(smem + SM_LABC);
    const int* labR = (const int*)(smem + SM_LABR);
    unsigned* smaxr = (unsigned*)(smem + SM_MAXR);
    unsigned* smaxc = (unsigned*)(smem + SM_MAXC);

    // row-fold: f16 C frag layout: c[h] holds (row g + 8h, cols 2tg, 2tg+1)
#pragma unroll
    for (int mf = 0; mf < 4; mf++) {
#pragma unroll
        for (int h = 0; h < 2; h++) {
            int row = wm * 64 + mf * 16 + g + h * 8;
            int rl = labR[row];
            float m = NEG_INF;
#pragma unroll
            for (int nfi = 0; nfi < 8; nfi++) {
                int col = wn * 64 + nfi * 8 + 2 * tg;
                float2 f = __half22float2(*(__half2*)&acc[mf][nfi][h]);
                if (labC[col] != rl)     m = fmaxf(m, f.x);
                if (labC[col + 1] != rl) m = fmaxf(m, f.y);
            }
            atomicMax(&smaxr[row], enc_f(m));
        }
    }

    // col-fold (mirror of symmetric src0 tiles)
    if (cf_any) {
#pragma unroll
        for (int nfi = 0; nfi < 8; nfi++) {
#pragma unroll
            for (int cpos = 0; cpos < 2; cpos++) {
                int col = wn * 64 + nfi * 8 + 2 * tg + cpos;
                int cl = labC[col];
                float m = NEG_INF;
#pragma unroll
                for (int mf = 0; mf < 4; mf++) {
#pragma unroll
                    for (int h = 0; h < 2; h++) {
                        int row = wm * 64 + mf * 16 + g + h * 8;
                        float2 f = __half22float2(*(__half2*)&acc[mf][nfi][h]);
                        float v = cpos ? f.y : f.x;
                        if (labR[row] != cl) m = fmaxf(m, v);
                    }
                }
#pragma unroll
                for (int o = 4; o < 32; o <<= 1) m = fmaxf(m, __shfl_xor_sync(0xffffffffu, m, o));
                if (g == 0 && (2 * cpair + (col >> 7)) > rtile)
                    atomicMax(&smaxc[col], enc_f(m));
            }
        }
    }

    __syncthreads();
    if (tid < TILE_M) {
        unsigned e = smaxr[tid];
        int grow = row0 + tid;
        if (src == 0) {
            atomicMax(&g_maxbits[0][grow], e);
            atomicMax(&g_maxbits[1][grow], e);
        } else {
            atomicMax(&g_maxbits[src - 1][grow], e);
        }
    }
    if (src == 0) {
        int colblock = 2 * cpair + (tid >> 7);
        if (colblock > rtile) {
            unsigned ec = smaxc[tid];
            int gcol = colbase + tid;
            atomicMax(&g_maxbits[0][gcol], ec);
            atomicMax(&g_maxbits[1][gcol], ec);
        }
    }
}

// ---------------- kernel 3: fused loss + reduction (single block) ----------------
__global__ void loss_kernel(float* __restrict__ out) {
    int tid = threadIdx.x;                 // 0..1023
    float s = 0.f;
#pragma unroll
    for (int k = 0; k < 8; k++) {
        int idx = tid + k * 1024;
        int v = idx >> 12;
        int i = idx & (BATCH - 1);
        float pd = g_posdot[v][i];
        float nd = dec_f(g_maxbits[v][i]);
        float pos = sqrtf(fmaxf(2.0f - 2.0f * pd, 1e-12f));
        float neg = sqrtf(fmaxf(2.0f - 2.0f * nd, 1e-12f));
        s += fmaxf(pos - neg + 1.0f, 0.0f);
    }
#pragma unroll
    for (int o = 16; o; o >>= 1) s += __shfl_down_sync(0xffffffffu, s, o);
    __shared__ float ws[32];
    if ((tid & 31) == 0) ws[tid >> 5] = s;
    __syncthreads();
    if (tid < 32) {
        float t = ws[tid];
#pragma unroll
        for (int o = 16; o; o >>= 1) t += __shfl_down_sync(0xffffffffu, t, o);
        if (tid == 0) out[0] = t * (1.0f / 8192.0f);
    }
}

// ---------------------------------------------------------------------------
extern "C" void kernel_launch(void* const* d_in, const int* in_sizes, int n_in,
                              void* d_out, int out_size) {
    const float* anchor = (const float*)d_in[0];
    const float* positive = (const float*)d_in[1];
    const int* labels = (const int*)d_in[2];

    cudaFuncSetAttribute(gemm_max_kernel, cudaFuncAttributeMaxDynamicSharedMemorySize, SM_TOTAL);

    norm_kernel<<<BATCH, 64>>>(anchor, positive);
    gemm_max_kernel<<<1296, 256, SM_TOTAL>>>(labels);
    loss_kernel<<<1, 1024>>>((float*)d_out);
}